// round 2
// baseline (speedup 1.0000x reference)
#include <cuda_runtime.h>
#include <float.h>

// Problem constants
#define BB   2
#define SS   2048
#define HIDD 2048
#define NH   32
#define NKV  8
#define HD   64
#define MROWS (BB*SS)          // 4096
#define SCALE 0.125f           // HD^-0.5
#define EPS   1e-6f

// ---------------- scratch (static device allocations are allowed) -------------
__device__ float g_q[(size_t)MROWS * NH * HD];    // (4096, 2048)
__device__ float g_k[(size_t)MROWS * NKV * HD];   // (4096, 512)
__device__ float g_v[(size_t)MROWS * NKV * HD];   // (4096, 512)
__device__ float g_attn[(size_t)MROWS * NH * HD]; // (4096, 2048)

// ---------------- fp32 tiled GEMM:  C[M][N] = A[M][K] @ B[N][K]^T -------------
// 64x64 tile, BK=16, 256 threads, 4x4 micro-tile per thread.
#define GT 64
#define GBK 16
__global__ __launch_bounds__(256) void gemm_abT(
    const float* __restrict__ A, const float* __restrict__ Bm,
    float* __restrict__ C, int M, int N, int K)
{
    __shared__ float As[GBK][GT];
    __shared__ float Bs[GBK][GT];

    const int t  = threadIdx.x;
    const int tx = t & 15;        // 0..15
    const int ty = t >> 4;        // 0..15
    const int m0 = blockIdx.y * GT;
    const int n0 = blockIdx.x * GT;

    // loader mapping: each thread loads one float4 of A and one of B per k-step
    const int lr = t >> 2;        // row in tile 0..63
    const int lc = (t & 3) * 4;   // k offset 0,4,8,12

    float acc[4][4];
#pragma unroll
    for (int i = 0; i < 4; i++)
#pragma unroll
        for (int j = 0; j < 4; j++) acc[i][j] = 0.f;

    const float* Ap = A + (size_t)(m0 + lr) * K + lc;
    const float* Bp = Bm + (size_t)(n0 + lr) * K + lc;

    for (int k0 = 0; k0 < K; k0 += GBK) {
        float4 av = *reinterpret_cast<const float4*>(Ap + k0);
        float4 bv = *reinterpret_cast<const float4*>(Bp + k0);
        As[lc + 0][lr] = av.x; As[lc + 1][lr] = av.y;
        As[lc + 2][lr] = av.z; As[lc + 3][lr] = av.w;
        Bs[lc + 0][lr] = bv.x; Bs[lc + 1][lr] = bv.y;
        Bs[lc + 2][lr] = bv.z; Bs[lc + 3][lr] = bv.w;
        __syncthreads();

#pragma unroll
        for (int kk = 0; kk < GBK; kk++) {
            float4 a = *reinterpret_cast<const float4*>(&As[kk][ty * 4]);
            float4 b = *reinterpret_cast<const float4*>(&Bs[kk][tx * 4]);
            acc[0][0] += a.x * b.x; acc[0][1] += a.x * b.y; acc[0][2] += a.x * b.z; acc[0][3] += a.x * b.w;
            acc[1][0] += a.y * b.x; acc[1][1] += a.y * b.y; acc[1][2] += a.y * b.z; acc[1][3] += a.y * b.w;
            acc[2][0] += a.z * b.x; acc[2][1] += a.z * b.y; acc[2][2] += a.z * b.z; acc[2][3] += a.z * b.w;
            acc[3][0] += a.w * b.x; acc[3][1] += a.w * b.y; acc[3][2] += a.w * b.z; acc[3][3] += a.w * b.w;
        }
        __syncthreads();
    }

#pragma unroll
    for (int i = 0; i < 4; i++) {
        float4 r = make_float4(acc[i][0], acc[i][1], acc[i][2], acc[i][3]);
        *reinterpret_cast<float4*>(C + (size_t)(m0 + ty * 4 + i) * N + n0 + tx * 4) = r;
    }
}

// ---------------- RMSNorm + RoPE over q and k head-rows (64 elems each) -------
// One warp per head-row. Lane handles elements d=lane and d=lane+32.
__global__ void norm_rope_kernel(
    const float* __restrict__ cosv, const float* __restrict__ sinv,
    const float* __restrict__ qw,   const float* __restrict__ kw)
{
    const int gid  = blockIdx.x * blockDim.x + threadIdx.x;
    const int wid  = gid >> 5;
    const int lane = gid & 31;
    const int nqr  = MROWS * NH;            // q head-rows
    const int ntot = nqr + MROWS * NKV;
    if (wid >= ntot) return;

    float* base;
    int bs;
    const float* w;
    if (wid < nqr) { base = g_q + (size_t)wid * HD;           bs = wid / NH;  w = qw; }
    else { int r = wid - nqr; base = g_k + (size_t)r * HD;    bs = r / NKV;   w = kw; }

    float x0 = base[lane];
    float x1 = base[lane + 32];
    float ss = x0 * x0 + x1 * x1;
#pragma unroll
    for (int o = 16; o > 0; o >>= 1) ss += __shfl_xor_sync(0xffffffffu, ss, o);
    const float rinv = rsqrtf(ss * (1.0f / HD) + EPS);

    const float n0 = w[lane]      * (x0 * rinv);
    const float n1 = w[lane + 32] * (x1 * rinv);

    const float c0 = cosv[(size_t)bs * HD + lane];
    const float c1 = cosv[(size_t)bs * HD + lane + 32];
    const float s0 = sinv[(size_t)bs * HD + lane];
    const float s1 = sinv[(size_t)bs * HD + lane + 32];

    base[lane]      = n0 * c0 - n1 * s0;   // rotate_half: -x2 for d<32
    base[lane + 32] = n1 * c1 + n0 * s1;   //  x1 for d>=32
}

// ---------------- causal flash attention (fp32, per-thread query row) ---------
#define FBQ 128
#define FBK 64
__global__ __launch_bounds__(FBQ) void flash_kernel()
{
    const int bh  = blockIdx.y;           // 0..B*NH-1
    const int b   = bh / NH;
    const int h   = bh % NH;
    const int kvh = h / (NH / NKV);
    const int q0  = blockIdx.x * FBQ;
    const int tid = threadIdx.x;          // 0..127
    const int qi  = q0 + tid;

    __shared__ float Ks[FBK][HD];
    __shared__ float Vs[FBK][HD];

    float4 qr[16], acc[16];
    const float4* qp = reinterpret_cast<const float4*>(
        g_q + ((size_t)(b * SS + qi) * NH + h) * HD);
#pragma unroll
    for (int i = 0; i < 16; i++) { qr[i] = qp[i]; acc[i] = make_float4(0.f, 0.f, 0.f, 0.f); }

    float m = -FLT_MAX, l = 0.f;
    const int kend = q0 + FBQ;            // exclusive upper bound of needed keys

    for (int k0 = 0; k0 < kend; k0 += FBK) {
        // cooperative tile load (float4, coalesced)
        for (int idx = tid; idx < FBK * (HD / 4); idx += FBQ) {
            const int row = idx >> 4;            // /16
            const int c   = idx & 15;
            const size_t g = ((size_t)(b * SS + k0 + row) * NKV + kvh) * HD + c * 4;
            reinterpret_cast<float4*>(&Ks[row][0])[c] = *reinterpret_cast<const float4*>(g_k + g);
            reinterpret_cast<float4*>(&Vs[row][0])[c] = *reinterpret_cast<const float4*>(g_v + g);
        }
        __syncthreads();

#pragma unroll 2
        for (int j = 0; j < FBK; j++) {
            const float4* kr = reinterpret_cast<const float4*>(&Ks[j][0]);
            float s = 0.f;
#pragma unroll
            for (int i = 0; i < 16; i++) {
                float4 kv = kr[i];
                s += qr[i].x * kv.x + qr[i].y * kv.y + qr[i].z * kv.z + qr[i].w * kv.w;
            }
            const float sc = (k0 + j <= qi) ? s * SCALE : -FLT_MAX;
            if (sc > m) {                      // rare: lazy rescale on new max
                const float corr = __expf(m - sc);
                l *= corr;
#pragma unroll
                for (int i = 0; i < 16; i++) {
                    acc[i].x *= corr; acc[i].y *= corr;
                    acc[i].z *= corr; acc[i].w *= corr;
                }
                m = sc;
            }
            const float p = __expf(sc - m);    // masked keys -> exp(-huge)=0
            l += p;
            const float4* vr = reinterpret_cast<const float4*>(&Vs[j][0]);
#pragma unroll
            for (int i = 0; i < 16; i++) {
                float4 vv = vr[i];
                acc[i].x += p * vv.x; acc[i].y += p * vv.y;
                acc[i].z += p * vv.z; acc[i].w += p * vv.w;
            }
        }
        __syncthreads();
    }

    const float inv = 1.f / l;
    float4* op = reinterpret_cast<float4*>(
        g_attn + ((size_t)(b * SS + qi) * NH + h) * HD);
#pragma unroll
    for (int i = 0; i < 16; i++) {
        float4 r = acc[i];
        r.x *= inv; r.y *= inv; r.z *= inv; r.w *= inv;
        op[i] = r;
    }
}

// ------------------------------- launch ---------------------------------------
extern "C" void kernel_launch(void* const* d_in, const int* in_sizes, int n_in,
                              void* d_out, int out_size)
{
    const float* hidden = (const float*)d_in[0];
    const float* cosv   = (const float*)d_in[1];
    const float* sinv   = (const float*)d_in[2];
    const float* Wq     = (const float*)d_in[3];
    const float* Wk     = (const float*)d_in[4];
    const float* Wv     = (const float*)d_in[5];
    const float* Wo     = (const float*)d_in[6];
    const float* qw     = (const float*)d_in[7];
    const float* kw     = (const float*)d_in[8];
    float* out          = (float*)d_out;

    float *pq, *pk, *pv, *pattn;
    cudaGetSymbolAddress((void**)&pq,    g_q);
    cudaGetSymbolAddress((void**)&pk,    g_k);
    cudaGetSymbolAddress((void**)&pv,    g_v);
    cudaGetSymbolAddress((void**)&pattn, g_attn);

    // QKV projections: (4096,2048) @ W^T
    gemm_abT<<<dim3((NH  * HD) / GT, MROWS / GT), 256>>>(hidden, Wq, pq, MROWS, NH  * HD, HIDD);
    gemm_abT<<<dim3((NKV * HD) / GT, MROWS / GT), 256>>>(hidden, Wk, pk, MROWS, NKV * HD, HIDD);
    gemm_abT<<<dim3((NKV * HD) / GT, MROWS / GT), 256>>>(hidden, Wv, pv, MROWS, NKV * HD, HIDD);

    // RMSNorm + RoPE on q and k
    {
        const int warps = MROWS * NH + MROWS * NKV;     // head-rows
        const int threads = warps * 32;
        norm_rope_kernel<<<(threads + 255) / 256, 256>>>(cosv, sinv, qw, kw);
    }

    // causal flash attention
    flash_kernel<<<dim3(SS / FBQ, BB * NH), FBQ>>>();

    // output projection -> d_out
    gemm_abT<<<dim3(HIDD / GT, MROWS / GT), 256>>>(pattn, Wo, out, MROWS, HIDD, NH * HD);
}

// round 3
// speedup vs baseline: 1.3090x; 1.3090x over previous
#include <cuda_runtime.h>
#include <float.h>
#include <stdint.h>

// Problem constants
#define BB   2
#define SS   2048
#define HIDD 2048
#define NH   32
#define NKV  8
#define HD   64
#define MROWS (BB*SS)          // 4096
#define SCALE 0.125f           // HD^-0.5
#define EPS   1e-6f

// ---------------- scratch -----------------------------------------------------
__device__ float g_q[(size_t)MROWS * NH * HD];    // (4096, 2048)
__device__ float g_k[(size_t)MROWS * NKV * HD];   // (4096, 512)
__device__ float g_v[(size_t)MROWS * NKV * HD];   // (4096, 512)
__device__ float g_attn[(size_t)MROWS * NH * HD]; // (4096, 2048)

// ---------------- TF32 helpers ------------------------------------------------
__device__ __forceinline__ void split_tf32(float x, uint32_t& hi, uint32_t& lo) {
    uint32_t h;
    asm("cvt.rna.tf32.f32 %0, %1;" : "=r"(h) : "f"(x));
    float r = x - __uint_as_float(h);
    uint32_t l;
    asm("cvt.rna.tf32.f32 %0, %1;" : "=r"(l) : "f"(r));
    hi = h; lo = l;
}

__device__ __forceinline__ void mma_tf32(float c[4],
    uint32_t a0, uint32_t a1, uint32_t a2, uint32_t a3,
    uint32_t b0, uint32_t b1)
{
    asm volatile(
        "mma.sync.aligned.m16n8k8.row.col.f32.tf32.tf32.f32 "
        "{%0,%1,%2,%3}, {%4,%5,%6,%7}, {%8,%9}, {%0,%1,%2,%3};"
        : "+f"(c[0]), "+f"(c[1]), "+f"(c[2]), "+f"(c[3])
        : "r"(a0), "r"(a1), "r"(a2), "r"(a3), "r"(b0), "r"(b1));
}

// ---------------- 3xTF32 tensor-core GEMM:  C = A[M,K] @ B[N,K]^T --------------
// Block tile 128x128, BK=16, 256 threads (8 warps), warp tile 64x32.
#define TBM 128
#define TBN 128
#define TBK 16
#define SPAD 20   // row stride in floats (16 + 4 pad, conflict-free fragment loads)

__global__ __launch_bounds__(256) void gemm_tc(
    const float* __restrict__ A, const float* __restrict__ Bm,
    float* __restrict__ C, int M, int N, int K)
{
    __shared__ float As[TBM][SPAD];
    __shared__ float Bs[TBN][SPAD];

    const int t    = threadIdx.x;
    const int lane = t & 31;
    const int warp = t >> 5;                  // 0..7
    const int wm   = warp & 1;                // 2 warps along M
    const int wn   = warp >> 1;               // 4 warps along N
    const int m0   = blockIdx.y * TBM;
    const int n0   = blockIdx.x * TBN;

    const int grp = lane >> 2;                // 0..7
    const int kc  = lane & 3;                 // 0..3

    // gmem loader mapping: each thread loads 2 float4 of A and 2 of B per tile
    const int lr = t >> 2;                    // 0..63
    const int lq = (t & 3) * 4;               // k offset 0,4,8,12
    const float* Ap0 = A  + (size_t)(m0 + lr)      * K + lq;
    const float* Ap1 = A  + (size_t)(m0 + lr + 64) * K + lq;
    const float* Bp0 = Bm + (size_t)(n0 + lr)      * K + lq;
    const float* Bp1 = Bm + (size_t)(n0 + lr + 64) * K + lq;

    float acc[4][4][4];                       // [mt][nt][frag]
#pragma unroll
    for (int i = 0; i < 4; i++)
#pragma unroll
        for (int j = 0; j < 4; j++)
#pragma unroll
            for (int f = 0; f < 4; f++) acc[i][j][f] = 0.f;

    // preload tile 0
    float4 ra0 = *reinterpret_cast<const float4*>(Ap0);
    float4 ra1 = *reinterpret_cast<const float4*>(Ap1);
    float4 rb0 = *reinterpret_cast<const float4*>(Bp0);
    float4 rb1 = *reinterpret_cast<const float4*>(Bp1);
    *reinterpret_cast<float4*>(&As[lr][lq])      = ra0;
    *reinterpret_cast<float4*>(&As[lr + 64][lq]) = ra1;
    *reinterpret_cast<float4*>(&Bs[lr][lq])      = rb0;
    *reinterpret_cast<float4*>(&Bs[lr + 64][lq]) = rb1;
    __syncthreads();

    const int mrow = wm * 64 + grp;           // A fragment base row
    const int nrow = wn * 32 + grp;           // B fragment base row

    for (int k0 = TBK; ; k0 += TBK) {
        const bool more = (k0 < K);
        if (more) {
            ra0 = *reinterpret_cast<const float4*>(Ap0 + k0);
            ra1 = *reinterpret_cast<const float4*>(Ap1 + k0);
            rb0 = *reinterpret_cast<const float4*>(Bp0 + k0);
            rb1 = *reinterpret_cast<const float4*>(Bp1 + k0);
        }

#pragma unroll
        for (int ks = 0; ks < TBK; ks += 8) {
            uint32_t ahi[4][4], alo[4][4];
#pragma unroll
            for (int mt = 0; mt < 4; mt++) {
                const int r = mrow + mt * 16;
                split_tf32(As[r][ks + kc],          ahi[mt][0], alo[mt][0]);
                split_tf32(As[r + 8][ks + kc],      ahi[mt][1], alo[mt][1]);
                split_tf32(As[r][ks + kc + 4],      ahi[mt][2], alo[mt][2]);
                split_tf32(As[r + 8][ks + kc + 4],  ahi[mt][3], alo[mt][3]);
            }
            uint32_t bhi[4][2], blo[4][2];
#pragma unroll
            for (int nt = 0; nt < 4; nt++) {
                const int n = nrow + nt * 8;
                split_tf32(Bs[n][ks + kc],     bhi[nt][0], blo[nt][0]);
                split_tf32(Bs[n][ks + kc + 4], bhi[nt][1], blo[nt][1]);
            }
#pragma unroll
            for (int mt = 0; mt < 4; mt++)
#pragma unroll
                for (int nt = 0; nt < 4; nt++) {
                    mma_tf32(acc[mt][nt], ahi[mt][0], ahi[mt][1], ahi[mt][2], ahi[mt][3],
                             bhi[nt][0], bhi[nt][1]);
                    mma_tf32(acc[mt][nt], alo[mt][0], alo[mt][1], alo[mt][2], alo[mt][3],
                             bhi[nt][0], bhi[nt][1]);
                    mma_tf32(acc[mt][nt], ahi[mt][0], ahi[mt][1], ahi[mt][2], ahi[mt][3],
                             blo[nt][0], blo[nt][1]);
                }
        }
        __syncthreads();
        if (!more) break;
        *reinterpret_cast<float4*>(&As[lr][lq])      = ra0;
        *reinterpret_cast<float4*>(&As[lr + 64][lq]) = ra1;
        *reinterpret_cast<float4*>(&Bs[lr][lq])      = rb0;
        *reinterpret_cast<float4*>(&Bs[lr + 64][lq]) = rb1;
        __syncthreads();
    }

    // epilogue
#pragma unroll
    for (int mt = 0; mt < 4; mt++) {
        const int row = m0 + wm * 64 + mt * 16 + grp;
#pragma unroll
        for (int nt = 0; nt < 4; nt++) {
            const int col = n0 + wn * 32 + nt * 8 + kc * 2;
            *reinterpret_cast<float2*>(C + (size_t)row * N + col) =
                make_float2(acc[mt][nt][0], acc[mt][nt][1]);
            *reinterpret_cast<float2*>(C + (size_t)(row + 8) * N + col) =
                make_float2(acc[mt][nt][2], acc[mt][nt][3]);
        }
    }
}

// ---------------- RMSNorm + RoPE over q and k head-rows -----------------------
__global__ void norm_rope_kernel(
    const float* __restrict__ cosv, const float* __restrict__ sinv,
    const float* __restrict__ qw,   const float* __restrict__ kw)
{
    const int gid  = blockIdx.x * blockDim.x + threadIdx.x;
    const int wid  = gid >> 5;
    const int lane = gid & 31;
    const int nqr  = MROWS * NH;
    const int ntot = nqr + MROWS * NKV;
    if (wid >= ntot) return;

    float* base;
    int bs;
    const float* w;
    if (wid < nqr) { base = g_q + (size_t)wid * HD;        bs = wid / NH;  w = qw; }
    else { int r = wid - nqr; base = g_k + (size_t)r * HD; bs = r / NKV;   w = kw; }

    float x0 = base[lane];
    float x1 = base[lane + 32];
    float ss = x0 * x0 + x1 * x1;
#pragma unroll
    for (int o = 16; o > 0; o >>= 1) ss += __shfl_xor_sync(0xffffffffu, ss, o);
    const float rinv = rsqrtf(ss * (1.0f / HD) + EPS);

    const float n0 = w[lane]      * (x0 * rinv);
    const float n1 = w[lane + 32] * (x1 * rinv);

    const float c0 = cosv[(size_t)bs * HD + lane];
    const float c1 = cosv[(size_t)bs * HD + lane + 32];
    const float s0 = sinv[(size_t)bs * HD + lane];
    const float s1 = sinv[(size_t)bs * HD + lane + 32];

    base[lane]      = n0 * c0 - n1 * s0;
    base[lane + 32] = n1 * c1 + n0 * s1;
}

// ---------------- causal flash attention (fp32, per-thread query row) ---------
#define FBQ 128
#define FBK 64
__global__ __launch_bounds__(FBQ) void flash_kernel()
{
    const int bh  = blockIdx.y;
    const int b   = bh / NH;
    const int h   = bh % NH;
    const int kvh = h / (NH / NKV);
    const int q0  = blockIdx.x * FBQ;
    const int tid = threadIdx.x;
    const int qi  = q0 + tid;

    __shared__ float Ks[FBK][HD];
    __shared__ float Vs[FBK][HD];

    float4 qr[16], acc[16];
    const float4* qp = reinterpret_cast<const float4*>(
        g_q + ((size_t)(b * SS + qi) * NH + h) * HD);
#pragma unroll
    for (int i = 0; i < 16; i++) { qr[i] = qp[i]; acc[i] = make_float4(0.f, 0.f, 0.f, 0.f); }

    float m = -FLT_MAX, l = 0.f;
    const int kend = q0 + FBQ;

    for (int k0 = 0; k0 < kend; k0 += FBK) {
        for (int idx = tid; idx < FBK * (HD / 4); idx += FBQ) {
            const int row = idx >> 4;
            const int c   = idx & 15;
            const size_t g = ((size_t)(b * SS + k0 + row) * NKV + kvh) * HD + c * 4;
            reinterpret_cast<float4*>(&Ks[row][0])[c] = *reinterpret_cast<const float4*>(g_k + g);
            reinterpret_cast<float4*>(&Vs[row][0])[c] = *reinterpret_cast<const float4*>(g_v + g);
        }
        __syncthreads();

#pragma unroll 2
        for (int j = 0; j < FBK; j++) {
            const float4* kr = reinterpret_cast<const float4*>(&Ks[j][0]);
            float s = 0.f;
#pragma unroll
            for (int i = 0; i < 16; i++) {
                float4 kv = kr[i];
                s += qr[i].x * kv.x + qr[i].y * kv.y + qr[i].z * kv.z + qr[i].w * kv.w;
            }
            const float sc = (k0 + j <= qi) ? s * SCALE : -FLT_MAX;
            if (sc > m) {
                const float corr = __expf(m - sc);
                l *= corr;
#pragma unroll
                for (int i = 0; i < 16; i++) {
                    acc[i].x *= corr; acc[i].y *= corr;
                    acc[i].z *= corr; acc[i].w *= corr;
                }
                m = sc;
            }
            const float p = __expf(sc - m);
            l += p;
            const float4* vr = reinterpret_cast<const float4*>(&Vs[j][0]);
#pragma unroll
            for (int i = 0; i < 16; i++) {
                float4 vv = vr[i];
                acc[i].x += p * vv.x; acc[i].y += p * vv.y;
                acc[i].z += p * vv.z; acc[i].w += p * vv.w;
            }
        }
        __syncthreads();
    }

    const float inv = 1.f / l;
    float4* op = reinterpret_cast<float4*>(
        g_attn + ((size_t)(b * SS + qi) * NH + h) * HD);
#pragma unroll
    for (int i = 0; i < 16; i++) {
        float4 r = acc[i];
        r.x *= inv; r.y *= inv; r.z *= inv; r.w *= inv;
        op[i] = r;
    }
}

// ------------------------------- launch ---------------------------------------
extern "C" void kernel_launch(void* const* d_in, const int* in_sizes, int n_in,
                              void* d_out, int out_size)
{
    const float* hidden = (const float*)d_in[0];
    const float* cosv   = (const float*)d_in[1];
    const float* sinv   = (const float*)d_in[2];
    const float* Wq     = (const float*)d_in[3];
    const float* Wk     = (const float*)d_in[4];
    const float* Wv     = (const float*)d_in[5];
    const float* Wo     = (const float*)d_in[6];
    const float* qw     = (const float*)d_in[7];
    const float* kw     = (const float*)d_in[8];
    float* out          = (float*)d_out;

    float *pq, *pk, *pv, *pattn;
    cudaGetSymbolAddress((void**)&pq,    g_q);
    cudaGetSymbolAddress((void**)&pk,    g_k);
    cudaGetSymbolAddress((void**)&pv,    g_v);
    cudaGetSymbolAddress((void**)&pattn, g_attn);

    // QKV projections (tensor-core 3xTF32)
    gemm_tc<<<dim3((NH  * HD) / TBN, MROWS / TBM), 256>>>(hidden, Wq, pq, MROWS, NH  * HD, HIDD);
    gemm_tc<<<dim3((NKV * HD) / TBN, MROWS / TBM), 256>>>(hidden, Wk, pk, MROWS, NKV * HD, HIDD);
    gemm_tc<<<dim3((NKV * HD) / TBN, MROWS / TBM), 256>>>(hidden, Wv, pv, MROWS, NKV * HD, HIDD);

    // RMSNorm + RoPE on q and k
    {
        const int warps = MROWS * NH + MROWS * NKV;
        const int threads = warps * 32;
        norm_rope_kernel<<<(threads + 255) / 256, 256>>>(cosv, sinv, qw, kw);
    }

    // causal flash attention
    flash_kernel<<<dim3(SS / FBQ, BB * NH), FBQ>>>();

    // output projection -> d_out
    gemm_tc<<<dim3(HIDD / TBN, MROWS / TBM), 256>>>(pattn, Wo, out, MROWS, HIDD, NH * HD);
}